// round 1
// baseline (speedup 1.0000x reference)
#include <cuda_runtime.h>
#include <cuda_bf16.h>
#include <math.h>

// Problem constants
#define BATCH   2048        // batch * windows
#define NTOK    49          // tokens per window
#define DIM     512
#define NHEAD   16
#define HDIM    32
#define NW      64          // windows per image (mask dim 0)
#define MROWS   (BATCH * NTOK)   // 100352
#define QKVCOLS (3 * DIM)        // 1536

// Scratch (device globals — no cudaMalloc allowed)
__device__ float g_qkv[(size_t)MROWS * QKVCOLS];   // [100352, 1536]  (3,H,HD packed in cols)
__device__ float g_att[(size_t)MROWS * DIM];       // [100352, 512]   attention output, (n, h*32+d)

// ---------------------------------------------------------------------------
// SGEMM + bias: C[M,N] = A[M,K] @ B[K,N] + bias[N]
// BM=BN=128, BK=8, 256 threads, 8x8 microtile. M,N multiples of 128, K mult of 8.
// ---------------------------------------------------------------------------
__global__ __launch_bounds__(256, 2)
void sgemm_bias_kernel(const float* __restrict__ A,
                       const float* __restrict__ B,
                       const float* __restrict__ bias,
                       float* __restrict__ C,
                       int M, int N, int K) {
    constexpr int BM = 128, BN = 128, BK = 8, TM = 8, TN = 8;
    __shared__ float As[BK][BM];
    __shared__ float Bs[BK][BN];

    const int tid = threadIdx.x;
    const int tx = tid % 16;          // 16 threads across N
    const int ty = tid / 16;          // 16 threads across M
    const int bx = blockIdx.x;        // N tile
    const int by = blockIdx.y;        // M tile

    const float* Ab = A + (size_t)by * BM * K;
    const float* Bb = B + (size_t)bx * BN;

    // Load mapping
    const int arow = tid >> 1;            // 0..127
    const int acol = (tid & 1) * 4;       // 0 or 4
    const int brow = tid >> 5;            // 0..7
    const int bcol = (tid & 31) * 4;      // 0..124

    float acc[TM][TN];
    #pragma unroll
    for (int i = 0; i < TM; i++)
        #pragma unroll
        for (int j = 0; j < TN; j++) acc[i][j] = 0.f;

    for (int k0 = 0; k0 < K; k0 += BK) {
        float4 a = *(const float4*)(Ab + (size_t)arow * K + k0 + acol);
        As[acol + 0][arow] = a.x;
        As[acol + 1][arow] = a.y;
        As[acol + 2][arow] = a.z;
        As[acol + 3][arow] = a.w;
        float4 b = *(const float4*)(Bb + (size_t)(k0 + brow) * N + bcol);
        *(float4*)&Bs[brow][bcol] = b;
        __syncthreads();

        #pragma unroll
        for (int k = 0; k < BK; k++) {
            float ar[TM], br[TN];
            #pragma unroll
            for (int i = 0; i < TM; i++) ar[i] = As[k][ty * TM + i];
            #pragma unroll
            for (int j = 0; j < TN; j++) br[j] = Bs[k][tx * TN + j];
            #pragma unroll
            for (int i = 0; i < TM; i++)
                #pragma unroll
                for (int j = 0; j < TN; j++)
                    acc[i][j] = fmaf(ar[i], br[j], acc[i][j]);
        }
        __syncthreads();
    }

    // Epilogue with bias
    #pragma unroll
    for (int i = 0; i < TM; i++) {
        const size_t row = (size_t)by * BM + ty * TM + i;
        #pragma unroll
        for (int j = 0; j < TN; j += 4) {
            const int col = bx * BN + tx * TN + j;
            float4 o;
            o.x = acc[i][j + 0] + bias[col + 0];
            o.y = acc[i][j + 1] + bias[col + 1];
            o.z = acc[i][j + 2] + bias[col + 2];
            o.w = acc[i][j + 3] + bias[col + 3];
            *(float4*)(C + row * N + col) = o;
        }
    }
}

// ---------------------------------------------------------------------------
// Window attention: one block per (window b, head h). 128 threads.
// qkv layout: row (b*49+n), col s*512 + h*32 + d  (s in {q,k,v})
// Output g_att: row (b*49+i), col h*32 + d
// ---------------------------------------------------------------------------
__global__ __launch_bounds__(128)
void window_attn_kernel(const float* __restrict__ qkv,
                        const float* __restrict__ mask,
                        const float* __restrict__ bias_table,
                        float* __restrict__ att_out) {
    const int b = blockIdx.x;
    const int h = blockIdx.y;
    const int tid = threadIdx.x;

    __shared__ float q[NTOK][HDIM];
    __shared__ float k[NTOK][HDIM];
    __shared__ float v[NTOK][HDIM];
    __shared__ float s[NTOK][NTOK + 1];

    const float scale = rsqrtf((float)HDIM);
    const size_t col0 = (size_t)h * HDIM;

    // Load q (pre-scaled), k, v
    for (int idx = tid; idx < NTOK * HDIM; idx += 128) {
        const int n = idx >> 5;
        const int d = idx & 31;
        const size_t row = (size_t)(b * NTOK + n) * QKVCOLS;
        q[n][d] = qkv[row + 0 * DIM + col0 + d] * scale;
        k[n][d] = qkv[row + 1 * DIM + col0 + d];
        v[n][d] = qkv[row + 2 * DIM + col0 + d];
    }
    __syncthreads();

    const float* mrow = mask + (size_t)(b & (NW - 1)) * NTOK * NTOK;

    // scores + relative-position bias + mask
    for (int p = tid; p < NTOK * NTOK; p += 128) {
        const int i = p / NTOK;
        const int j = p - i * NTOK;
        float acc = 0.f;
        #pragma unroll
        for (int d = 0; d < HDIM; d += 4) {
            acc = fmaf(q[i][d + 0], k[j][d + 0], acc);
            acc = fmaf(q[i][d + 1], k[j][d + 1], acc);
            acc = fmaf(q[i][d + 2], k[j][d + 2], acc);
            acc = fmaf(q[i][d + 3], k[j][d + 3], acc);
        }
        const int yi = i / 7, xi = i - yi * 7;
        const int yj = j / 7, xj = j - yj * 7;
        const int rel = (yi - yj + 6) * 13 + (xi - xj + 6);
        acc += bias_table[rel * NHEAD + h] + mrow[p];
        s[i][j] = acc;
    }
    __syncthreads();

    // Row softmax — one thread per row
    if (tid < NTOK) {
        float m = -1e30f;
        #pragma unroll 7
        for (int j = 0; j < NTOK; j++) m = fmaxf(m, s[tid][j]);
        float sum = 0.f;
        #pragma unroll 7
        for (int j = 0; j < NTOK; j++) {
            const float e = __expf(s[tid][j] - m);
            s[tid][j] = e;
            sum += e;
        }
        const float inv = 1.f / sum;
        #pragma unroll 7
        for (int j = 0; j < NTOK; j++) s[tid][j] *= inv;
    }
    __syncthreads();

    // out = softmax(scores) @ v
    for (int p = tid; p < NTOK * HDIM; p += 128) {
        const int i = p >> 5;
        const int d = p & 31;
        float acc = 0.f;
        #pragma unroll 7
        for (int j = 0; j < NTOK; j++)
            acc = fmaf(s[i][j], v[j][d], acc);
        att_out[(size_t)(b * NTOK + i) * DIM + col0 + d] = acc;
    }
}

// ---------------------------------------------------------------------------
extern "C" void kernel_launch(void* const* d_in, const int* in_sizes, int n_in,
                              void* d_out, int out_size) {
    const float* x          = (const float*)d_in[0];  // [2048,49,512]
    const float* mask       = (const float*)d_in[1];  // [64,49,49]
    const float* qkv_w      = (const float*)d_in[2];  // [512,1536]
    const float* qkv_b      = (const float*)d_in[3];  // [1536]
    const float* proj_w     = (const float*)d_in[4];  // [512,512]
    const float* proj_b     = (const float*)d_in[5];  // [512]
    const float* bias_table = (const float*)d_in[6];  // [169,16]
    float* out = (float*)d_out;

    float* qkv_s = nullptr;
    float* att_s = nullptr;
    cudaGetSymbolAddress((void**)&qkv_s, g_qkv);
    cudaGetSymbolAddress((void**)&att_s, g_att);

    // 1) QKV GEMM + bias: [100352,512] @ [512,1536]
    {
        dim3 grid(QKVCOLS / 128, MROWS / 128);
        sgemm_bias_kernel<<<grid, 256>>>(x, qkv_w, qkv_b, qkv_s,
                                         MROWS, QKVCOLS, DIM);
    }

    // 2) Window attention: one block per (window, head)
    {
        dim3 grid(BATCH, NHEAD);
        window_attn_kernel<<<grid, 128>>>(qkv_s, mask, bias_table, att_s);
    }

    // 3) Projection GEMM + bias: [100352,512] @ [512,512] -> d_out
    {
        dim3 grid(DIM / 128, MROWS / 128);
        sgemm_bias_kernel<<<grid, 256>>>(att_s, proj_w, proj_b, out,
                                         MROWS, DIM, DIM);
    }
}

// round 2
// speedup vs baseline: 1.4754x; 1.4754x over previous
#include <cuda_runtime.h>
#include <cuda_bf16.h>
#include <math.h>

// Problem constants
#define BATCH   2048
#define NTOK    49
#define DIM     512
#define NHEAD   16
#define HDIM    32
#define NW      64
#define MROWS   (BATCH * NTOK)   // 100352
#define QKVCOLS (3 * DIM)        // 1536

// Scratch (device globals — no cudaMalloc allowed)
__device__ float g_qkv[(size_t)MROWS * QKVCOLS];
__device__ float g_att[(size_t)MROWS * DIM];

// ---------------------------------------------------------------------------
// Double-buffered SGEMM + bias: C[M,N] = A[M,K] @ B[K,N] + bias[N]
// BM=BN=128, BK=16, 256 threads, 8x8 microtile.
// ---------------------------------------------------------------------------
__global__ __launch_bounds__(256, 2)
void sgemm_bias_kernel(const float* __restrict__ A,
                       const float* __restrict__ B,
                       const float* __restrict__ bias,
                       float* __restrict__ C,
                       int M, int N, int K) {
    constexpr int BM = 128, BN = 128, BK = 16, TM = 8, TN = 8;
    constexpr int AST = BM + 4;   // padded stride (keeps 16B alignment, cuts STS conflicts)
    __shared__ float As[2][BK][AST];
    __shared__ float Bs[2][BK][BN];

    const int tid = threadIdx.x;
    const int tx = tid & 15;
    const int ty = tid >> 4;
    const int bx = blockIdx.x;
    const int by = blockIdx.y;

    const float* Ab = A + (size_t)by * BM * K;
    const float* Bb = B + (size_t)bx * BN;

    // A tile: 128 rows x 16 cols = 512 float4 units; 2 per thread
    const int ar = tid >> 2;            // 0..63 (second load at +64)
    const int ac = (tid & 3) * 4;       // 0,4,8,12
    // B tile: 16 rows x 128 cols = 512 float4 units; 2 per thread
    const int br = tid >> 5;            // 0..7 (second at +8)
    const int bc = (tid & 31) * 4;

    float acc[TM][TN];
    #pragma unroll
    for (int i = 0; i < TM; i++)
        #pragma unroll
        for (int j = 0; j < TN; j++) acc[i][j] = 0.f;

    float4 pa0, pa1, pb0, pb1;

    // prologue: load tile 0
    pa0 = *(const float4*)(Ab + (size_t)ar * K + ac);
    pa1 = *(const float4*)(Ab + (size_t)(ar + 64) * K + ac);
    pb0 = *(const float4*)(Bb + (size_t)br * N + bc);
    pb1 = *(const float4*)(Bb + (size_t)(br + 8) * N + bc);

    As[0][ac + 0][ar] = pa0.x;  As[0][ac + 1][ar] = pa0.y;
    As[0][ac + 2][ar] = pa0.z;  As[0][ac + 3][ar] = pa0.w;
    As[0][ac + 0][ar + 64] = pa1.x;  As[0][ac + 1][ar + 64] = pa1.y;
    As[0][ac + 2][ar + 64] = pa1.z;  As[0][ac + 3][ar + 64] = pa1.w;
    *(float4*)&Bs[0][br][bc] = pb0;
    *(float4*)&Bs[0][br + 8][bc] = pb1;
    __syncthreads();

    int cur = 0;
    for (int k0 = 0; k0 < K; k0 += BK) {
        // prefetch next tile (clamped to 0 on last iter: valid address, discarded)
        const int kn = (k0 + BK < K) ? (k0 + BK) : 0;
        pa0 = *(const float4*)(Ab + (size_t)ar * K + kn + ac);
        pa1 = *(const float4*)(Ab + (size_t)(ar + 64) * K + kn + ac);
        pb0 = *(const float4*)(Bb + (size_t)(kn + br) * N + bc);
        pb1 = *(const float4*)(Bb + (size_t)(kn + br + 8) * N + bc);

        #pragma unroll
        for (int k = 0; k < BK; k++) {
            float4 a0 = *(float4*)&As[cur][k][ty * TM];
            float4 a1 = *(float4*)&As[cur][k][ty * TM + 4];
            float4 b0 = *(float4*)&Bs[cur][k][tx * TN];
            float4 b1 = *(float4*)&Bs[cur][k][tx * TN + 4];
            float arr[TM] = {a0.x, a0.y, a0.z, a0.w, a1.x, a1.y, a1.z, a1.w};
            float brr[TN] = {b0.x, b0.y, b0.z, b0.w, b1.x, b1.y, b1.z, b1.w};
            #pragma unroll
            for (int i = 0; i < TM; i++)
                #pragma unroll
                for (int j = 0; j < TN; j++)
                    acc[i][j] = fmaf(arr[i], brr[j], acc[i][j]);
        }

        const int nxt = cur ^ 1;
        As[nxt][ac + 0][ar] = pa0.x;  As[nxt][ac + 1][ar] = pa0.y;
        As[nxt][ac + 2][ar] = pa0.z;  As[nxt][ac + 3][ar] = pa0.w;
        As[nxt][ac + 0][ar + 64] = pa1.x;  As[nxt][ac + 1][ar + 64] = pa1.y;
        As[nxt][ac + 2][ar + 64] = pa1.z;  As[nxt][ac + 3][ar + 64] = pa1.w;
        *(float4*)&Bs[nxt][br][bc] = pb0;
        *(float4*)&Bs[nxt][br + 8][bc] = pb1;
        __syncthreads();
        cur = nxt;
    }

    #pragma unroll
    for (int i = 0; i < TM; i++) {
        const size_t row = (size_t)by * BM + ty * TM + i;
        #pragma unroll
        for (int j = 0; j < TN; j += 4) {
            const int col = bx * BN + tx * TN + j;
            float4 o;
            o.x = acc[i][j + 0] + bias[col + 0];
            o.y = acc[i][j + 1] + bias[col + 1];
            o.z = acc[i][j + 2] + bias[col + 2];
            o.w = acc[i][j + 3] + bias[col + 3];
            *(float4*)(C + row * N + col) = o;
        }
    }
}

// ---------------------------------------------------------------------------
// Window attention: one block per (window b, head h). 128 threads = 4 warps.
// K stored transposed in smem (conflict-free, stride 49 odd). 2-row tiling.
// ---------------------------------------------------------------------------
__global__ __launch_bounds__(128)
void window_attn_kernel(const float* __restrict__ qkv,
                        const float* __restrict__ mask,
                        const float* __restrict__ bias_table,
                        float* __restrict__ att_out) {
    const int b = blockIdx.x;
    const int h = blockIdx.y;
    const int tid = threadIdx.x;
    const int lane = tid & 31;
    const int wid = tid >> 5;

    __shared__ float q[NTOK][HDIM];
    __shared__ float kT[HDIM][NTOK];   // transposed
    __shared__ float v[NTOK][HDIM];
    __shared__ float s[NTOK][NTOK + 1];

    const float scale = rsqrtf((float)HDIM);
    const size_t col0 = (size_t)h * HDIM;

    // Load q (pre-scaled), kT, v
    for (int idx = tid; idx < NTOK * HDIM; idx += 128) {
        const int n = idx >> 5;
        const int d = idx & 31;
        const size_t row = (size_t)(b * NTOK + n) * QKVCOLS;
        q[n][d]  = qkv[row + 0 * DIM + col0 + d] * scale;
        kT[d][n] = qkv[row + 1 * DIM + col0 + d];
        v[n][d]  = qkv[row + 2 * DIM + col0 + d];
    }
    __syncthreads();

    const float* mrow = mask + (size_t)(b & (NW - 1)) * NTOK * NTOK;

    // Scores: pairs of rows per thread-item (halves kT traffic)
    // work units: 25 row-pairs x 49 cols = 1225
    for (int p = tid; p < 25 * NTOK; p += 128) {
        const int pr = p / NTOK;           // 0..24
        const int j  = p - pr * NTOK;      // 0..48
        const int i0 = pr * 2;
        const int i1 = i0 + 1;
        const bool has1 = (i1 < NTOK);
        const int i1r = has1 ? i1 : i0;

        float acc0 = 0.f, acc1 = 0.f;
        #pragma unroll
        for (int d = 0; d < HDIM; d++) {
            const float kk = kT[d][j];
            acc0 = fmaf(q[i0][d],  kk, acc0);
            acc1 = fmaf(q[i1r][d], kk, acc1);
        }
        const int yj = j / 7, xj = j - yj * 7;
        {
            const int yi = i0 / 7, xi = i0 - yi * 7;
            const int rel = (yi - yj + 6) * 13 + (xi - xj + 6);
            s[i0][j] = acc0 + bias_table[rel * NHEAD + h] + mrow[i0 * NTOK + j];
        }
        if (has1) {
            const int yi = i1 / 7, xi = i1 - yi * 7;
            const int rel = (yi - yj + 6) * 13 + (xi - xj + 6);
            s[i1][j] = acc1 + bias_table[rel * NHEAD + h] + mrow[i1 * NTOK + j];
        }
    }
    __syncthreads();

    // Warp-parallel softmax: one warp per row
    for (int r = wid; r < NTOK; r += 4) {
        const bool v2 = (lane + 32 < NTOK);
        float x0 = s[r][lane];
        float x1 = v2 ? s[r][lane + 32] : -1e30f;
        float m = fmaxf(x0, x1);
        #pragma unroll
        for (int off = 16; off > 0; off >>= 1)
            m = fmaxf(m, __shfl_xor_sync(0xffffffffu, m, off));
        float e0 = __expf(x0 - m);
        float e1 = v2 ? __expf(x1 - m) : 0.f;
        float sum = e0 + e1;
        #pragma unroll
        for (int off = 16; off > 0; off >>= 1)
            sum += __shfl_xor_sync(0xffffffffu, sum, off);
        const float inv = 1.f / sum;
        s[r][lane] = e0 * inv;
        if (v2) s[r][lane + 32] = e1 * inv;
    }
    __syncthreads();

    // out = P @ V, pairs of rows per thread-item (halves v traffic)
    // work units: 25 row-pairs x 32 dims = 800
    for (int p = tid; p < 25 * HDIM; p += 128) {
        const int i0 = (p >> 5) * 2;
        const int d  = p & 31;
        const int i1 = i0 + 1;
        const bool has1 = (i1 < NTOK);
        const int i1r = has1 ? i1 : i0;

        float acc0 = 0.f, acc1 = 0.f;
        #pragma unroll 7
        for (int j = 0; j < NTOK; j++) {
            const float vv = v[j][d];
            acc0 = fmaf(s[i0][j],  vv, acc0);
            acc1 = fmaf(s[i1r][j], vv, acc1);
        }
        att_out[(size_t)(b * NTOK + i0) * DIM + col0 + d] = acc0;
        if (has1)
            att_out[(size_t)(b * NTOK + i1) * DIM + col0 + d] = acc1;
    }
}

// ---------------------------------------------------------------------------
extern "C" void kernel_launch(void* const* d_in, const int* in_sizes, int n_in,
                              void* d_out, int out_size) {
    const float* x          = (const float*)d_in[0];
    const float* mask       = (const float*)d_in[1];
    const float* qkv_w      = (const float*)d_in[2];
    const float* qkv_b      = (const float*)d_in[3];
    const float* proj_w     = (const float*)d_in[4];
    const float* proj_b     = (const float*)d_in[5];
    const float* bias_table = (const float*)d_in[6];
    float* out = (float*)d_out;

    float* qkv_s = nullptr;
    float* att_s = nullptr;
    cudaGetSymbolAddress((void**)&qkv_s, g_qkv);
    cudaGetSymbolAddress((void**)&att_s, g_att);

    {   // QKV GEMM + bias
        dim3 grid(QKVCOLS / 128, MROWS / 128);
        sgemm_bias_kernel<<<grid, 256>>>(x, qkv_w, qkv_b, qkv_s,
                                         MROWS, QKVCOLS, DIM);
    }
    {   // attention
        dim3 grid(BATCH, NHEAD);
        window_attn_kernel<<<grid, 128>>>(qkv_s, mask, bias_table, att_s);
    }
    {   // proj GEMM + bias
        dim3 grid(DIM / 128, MROWS / 128);
        sgemm_bias_kernel<<<grid, 256>>>(att_s, proj_w, proj_b, out,
                                         MROWS, DIM, DIM);
    }
}

// round 4
// speedup vs baseline: 2.5824x; 1.7503x over previous
#include <cuda_runtime.h>
#include <cuda_bf16.h>
#include <cstdint>

#define BATCH   2048
#define NTOK    49
#define DIM     512
#define NHEAD   16
#define HDIM    32
#define NW      64
#define MROWS   (BATCH * NTOK)   // 100352 = 784 * 128
#define QKVCOLS (3 * DIM)        // 1536
#define KD      512

// Scratch (device globals — no cudaMalloc allowed)
__device__ __nv_bfloat16 g_xhi[(size_t)MROWS * KD];
__device__ __nv_bfloat16 g_xlo[(size_t)MROWS * KD];
__device__ __nv_bfloat16 g_wqh[QKVCOLS * KD];
__device__ __nv_bfloat16 g_wql[QKVCOLS * KD];
__device__ __nv_bfloat16 g_wph[DIM * KD];
__device__ __nv_bfloat16 g_wpl[DIM * KD];
__device__ float         g_qkv[(size_t)MROWS * QKVCOLS];
__device__ __nv_bfloat16 g_ahi[(size_t)MROWS * DIM];
__device__ __nv_bfloat16 g_alo[(size_t)MROWS * DIM];

// ---------------------------------------------------------------------------
// Helpers
// ---------------------------------------------------------------------------
__device__ __forceinline__ uint32_t smem_u32(const void* p) {
    uint32_t a;
    asm("{ .reg .u64 t; cvta.to.shared.u64 t, %1; cvt.u32.u64 %0, t; }"
        : "=r"(a) : "l"(p));
    return a;
}
__device__ __forceinline__ void cp16(uint32_t dst, const void* src) {
    asm volatile("cp.async.cg.shared.global [%0], [%1], 16;"
                 :: "r"(dst), "l"(src));
}
__device__ __forceinline__ void cp_commit() {
    asm volatile("cp.async.commit_group;" ::: "memory");
}
template <int N>
__device__ __forceinline__ void cp_wait() {
    asm volatile("cp.async.wait_group %0;" :: "n"(N) : "memory");
}
__device__ __forceinline__ void mma16816(float* c,
                                         uint32_t a0, uint32_t a1, uint32_t a2, uint32_t a3,
                                         uint32_t b0, uint32_t b1) {
    asm volatile(
        "mma.sync.aligned.m16n8k16.row.col.f32.bf16.bf16.f32 "
        "{%0,%1,%2,%3}, {%4,%5,%6,%7}, {%8,%9}, {%0,%1,%2,%3};"
        : "+f"(c[0]), "+f"(c[1]), "+f"(c[2]), "+f"(c[3])
        : "r"(a0), "r"(a1), "r"(a2), "r"(a3), "r"(b0), "r"(b1));
}

// ---------------------------------------------------------------------------
// Conversion kernels
// ---------------------------------------------------------------------------
__global__ void convert_x_kernel(const float* __restrict__ x,
                                 __nv_bfloat16* __restrict__ hi,
                                 __nv_bfloat16* __restrict__ lo, size_t n4) {
    size_t i = (size_t)blockIdx.x * blockDim.x + threadIdx.x;
    if (i >= n4) return;
    float4 v = ((const float4*)x)[i];
    __nv_bfloat16 h0 = __float2bfloat16(v.x);
    __nv_bfloat16 h1 = __float2bfloat16(v.y);
    __nv_bfloat16 h2 = __float2bfloat16(v.z);
    __nv_bfloat16 h3 = __float2bfloat16(v.w);
    __nv_bfloat162 hp0; hp0.x = h0; hp0.y = h1;
    __nv_bfloat162 hp1; hp1.x = h2; hp1.y = h3;
    ((__nv_bfloat162*)hi)[i * 2 + 0] = hp0;
    ((__nv_bfloat162*)hi)[i * 2 + 1] = hp1;
    __nv_bfloat162 lp0, lp1;
    lp0.x = __float2bfloat16(v.x - __bfloat162float(h0));
    lp0.y = __float2bfloat16(v.y - __bfloat162float(h1));
    lp1.x = __float2bfloat16(v.z - __bfloat162float(h2));
    lp1.y = __float2bfloat16(v.w - __bfloat162float(h3));
    ((__nv_bfloat162*)lo)[i * 2 + 0] = lp0;
    ((__nv_bfloat162*)lo)[i * 2 + 1] = lp1;
}

// w [K,N] fp32 -> hi/lo [N,K] bf16 (transposed)
__global__ void convert_w_kernel(const float* __restrict__ w,
                                 __nv_bfloat16* __restrict__ hi,
                                 __nv_bfloat16* __restrict__ lo, int K, int N) {
    int idx = blockIdx.x * blockDim.x + threadIdx.x;
    if (idx >= K * N) return;
    int n = idx / K, k = idx - n * K;
    float v = w[(size_t)k * N + n];
    __nv_bfloat16 h = __float2bfloat16(v);
    hi[idx] = h;
    lo[idx] = __float2bfloat16(v - __bfloat162float(h));
}

// ---------------------------------------------------------------------------
// Split-bf16 tensor-core GEMM via mma.sync:
//   C[M,N] = Ahi/lo[M,K] @ (Bhi/lo[N,K])^T + bias[N]  (fp32 out)
// CTA tile 128x128, BK=32, 256 threads (8 warps, 4x2), warp tile 32x64.
// cp.async 2-stage smem pipeline; fragments via direct LDS (stride-80B,
// conflict-free).
// ---------------------------------------------------------------------------
#define SM_STRIDE 80                 // bytes per smem row (32 bf16 + 8 pad)
#define SM_MAT    (128 * SM_STRIDE)  // 10240 B per matrix tile
#define SM_BUF    (4 * SM_MAT)       // AH, AL, BH, BL
#define GEMM_SMEM (2 * SM_BUF)       // double buffered: 81920 B

__global__ void __launch_bounds__(256, 2)
gemm_mma(const __nv_bfloat16* __restrict__ Ahi, const __nv_bfloat16* __restrict__ Alo,
         const __nv_bfloat16* __restrict__ Bhi, const __nv_bfloat16* __restrict__ Blo,
         const float* __restrict__ bias, float* __restrict__ C, int N) {
    extern __shared__ char sm[];
    const uint32_t smu = smem_u32(sm);

    const int tid  = threadIdx.x;
    const int lane = tid & 31;
    const int wid  = tid >> 5;
    const int wm   = wid & 3;          // 0..3 -> 32 rows each
    const int wn   = wid >> 2;         // 0..1 -> 64 cols each
    const int g    = lane >> 2;        // 0..7
    const int tg   = lane & 3;         // 0..3
    const int bn   = blockIdx.x, bm = blockIdx.y;

    const __nv_bfloat16* A_h = Ahi + (size_t)bm * 128 * KD;
    const __nv_bfloat16* A_l = Alo + (size_t)bm * 128 * KD;
    const __nv_bfloat16* B_h = Bhi + (size_t)bn * 128 * KD;
    const __nv_bfloat16* B_l = Blo + (size_t)bn * 128 * KD;

    // cp.async addressing for one 128x32 tile (8 KB per matrix):
    // u = tid + i*256 (i in 0..1): row = u>>2, c8 = (u&3)*8
    const int r0v = tid >> 2;                 // rows for u = tid
    const int r1v = (tid + 256) >> 2;         // rows for u = tid+256
    const int c0v = (tid & 3) * 8;
    const int c1v = c0v;                      // (u&3) identical for +256

    auto issue_tile = [&](int kt, int buf) {
        const int kof = kt * 32;
        const uint32_t sb = smu + buf * SM_BUF;
        const uint32_t o0 = (uint32_t)(r0v * SM_STRIDE + c0v * 2);
        const uint32_t o1 = (uint32_t)(r1v * SM_STRIDE + c1v * 2);
        const size_t g0 = (size_t)r0v * KD + kof + c0v;
        const size_t g1 = (size_t)r1v * KD + kof + c1v;
        cp16(sb + 0 * SM_MAT + o0, A_h + g0);
        cp16(sb + 0 * SM_MAT + o1, A_h + g1);
        cp16(sb + 1 * SM_MAT + o0, A_l + g0);
        cp16(sb + 1 * SM_MAT + o1, A_l + g1);
        cp16(sb + 2 * SM_MAT + o0, B_h + g0);
        cp16(sb + 2 * SM_MAT + o1, B_h + g1);
        cp16(sb + 3 * SM_MAT + o0, B_l + g0);
        cp16(sb + 3 * SM_MAT + o1, B_l + g1);
    };

    float acc[2][8][4];
    #pragma unroll
    for (int mt = 0; mt < 2; mt++)
        #pragma unroll
        for (int na = 0; na < 8; na++)
            #pragma unroll
            for (int r = 0; r < 4; r++) acc[mt][na][r] = 0.f;

    issue_tile(0, 0);
    cp_commit();

    const int NKT = KD / 32;   // 16
    for (int kt = 0; kt < NKT; kt++) {
        const int buf = kt & 1;
        if (kt + 1 < NKT) {
            issue_tile(kt + 1, buf ^ 1);
            cp_commit();
            cp_wait<1>();
        } else {
            cp_wait<0>();
        }
        __syncthreads();

        const char* sb = sm + buf * SM_BUF;
        const char* pAH = sb;
        const char* pAL = sb + SM_MAT;
        const char* pBH = sb + 2 * SM_MAT;
        const char* pBL = sb + 3 * SM_MAT;
        const int m0 = wm * 32;
        const int n0 = wn * 64;

        #pragma unroll
        for (int ks = 0; ks < 32; ks += 16) {
            const int ko = (ks + tg * 2) * 2;   // byte offset of k within row
            uint32_t aH[2][4], aL[2][4];
            #pragma unroll
            for (int mt = 0; mt < 2; mt++) {
                const int rb = (m0 + mt * 16 + g) * SM_STRIDE;
                aH[mt][0] = *(const uint32_t*)(pAH + rb + ko);
                aH[mt][1] = *(const uint32_t*)(pAH + rb + 8 * SM_STRIDE + ko);
                aH[mt][2] = *(const uint32_t*)(pAH + rb + ko + 16);
                aH[mt][3] = *(const uint32_t*)(pAH + rb + 8 * SM_STRIDE + ko + 16);
                aL[mt][0] = *(const uint32_t*)(pAL + rb + ko);
                aL[mt][1] = *(const uint32_t*)(pAL + rb + 8 * SM_STRIDE + ko);
                aL[mt][2] = *(const uint32_t*)(pAL + rb + ko + 16);
                aL[mt][3] = *(const uint32_t*)(pAL + rb + 8 * SM_STRIDE + ko + 16);
            }
            #pragma unroll
            for (int na = 0; na < 8; na++) {
                const int nb = (n0 + na * 8 + g) * SM_STRIDE;
                const uint32_t bH0 = *(const uint32_t*)(pBH + nb + ko);
                const uint32_t bH1 = *(const uint32_t*)(pBH + nb + ko + 16);
                const uint32_t bL0 = *(const uint32_t*)(pBL + nb + ko);
                const uint32_t bL1 = *(const uint32_t*)(pBL + nb + ko + 16);
                #pragma unroll
                for (int mt = 0; mt < 2; mt++) {
                    mma16816(acc[mt][na], aH[mt][0], aH[mt][1], aH[mt][2], aH[mt][3], bH0, bH1);
                    mma16816(acc[mt][na], aH[mt][0], aH[mt][1], aH[mt][2], aH[mt][3], bL0, bL1);
                    mma16816(acc[mt][na], aL[mt][0], aL[mt][1], aL[mt][2], aL[mt][3], bH0, bH1);
                }
            }
        }
        __syncthreads();
    }

    // Epilogue: direct STG.64 with bias
    #pragma unroll
    for (int mt = 0; mt < 2; mt++) {
        const int row0 = bm * 128 + wm * 32 + mt * 16 + g;
        #pragma unroll
        for (int na = 0; na < 8; na++) {
            const int col = bn * 128 + wn * 64 + na * 8 + tg * 2;
            const float b0 = __ldg(bias + col);
            const float b1 = __ldg(bias + col + 1);
            float2 o0, o1;
            o0.x = acc[mt][na][0] + b0;
            o0.y = acc[mt][na][1] + b1;
            o1.x = acc[mt][na][2] + b0;
            o1.y = acc[mt][na][3] + b1;
            *(float2*)(C + (size_t)row0 * N + col) = o0;
            *(float2*)(C + (size_t)(row0 + 8) * N + col) = o1;
        }
    }
}

// ---------------------------------------------------------------------------
// Window attention — emits bf16 hi/lo for the proj GEMM
// ---------------------------------------------------------------------------
__global__ __launch_bounds__(128)
void window_attn_kernel(const float* __restrict__ qkv,
                        const float* __restrict__ mask,
                        const float* __restrict__ bias_table,
                        __nv_bfloat16* __restrict__ ohi,
                        __nv_bfloat16* __restrict__ olo) {
    const int b = blockIdx.x;
    const int h = blockIdx.y;
    const int tid = threadIdx.x;
    const int lane = tid & 31;
    const int wid = tid >> 5;

    __shared__ float q[NTOK][HDIM];
    __shared__ float kT[HDIM][NTOK];
    __shared__ float v[NTOK][HDIM];
    __shared__ float s[NTOK][NTOK + 1];

    const float scale = rsqrtf((float)HDIM);
    const size_t col0 = (size_t)h * HDIM;

    for (int idx = tid; idx < NTOK * HDIM; idx += 128) {
        const int n = idx >> 5;
        const int d = idx & 31;
        const size_t row = (size_t)(b * NTOK + n) * QKVCOLS;
        q[n][d]  = qkv[row + 0 * DIM + col0 + d] * scale;
        kT[d][n] = qkv[row + 1 * DIM + col0 + d];
        v[n][d]  = qkv[row + 2 * DIM + col0 + d];
    }
    __syncthreads();

    const float* mrow = mask + (size_t)(b & (NW - 1)) * NTOK * NTOK;

    for (int p = tid; p < 25 * NTOK; p += 128) {
        const int pr = p / NTOK;
        const int j  = p - pr * NTOK;
        const int i0 = pr * 2;
        const int i1 = i0 + 1;
        const bool has1 = (i1 < NTOK);
        const int i1r = has1 ? i1 : i0;

        float acc0 = 0.f, acc1 = 0.f;
        #pragma unroll
        for (int d = 0; d < HDIM; d++) {
            const float kk = kT[d][j];
            acc0 = fmaf(q[i0][d],  kk, acc0);
            acc1 = fmaf(q[i1r][d], kk, acc1);
        }
        const int yj = j / 7, xj = j - yj * 7;
        {
            const int yi = i0 / 7, xi = i0 - yi * 7;
            const int rel = (yi - yj + 6) * 13 + (xi - xj + 6);
            s[i0][j] = acc0 + bias_table[rel * NHEAD + h] + mrow[i0 * NTOK + j];
        }
        if (has1) {
            const int yi = i1 / 7, xi = i1 - yi * 7;
            const int rel = (yi - yj + 6) * 13 + (xi - xj + 6);
            s[i1][j] = acc1 + bias_table[rel * NHEAD + h] + mrow[i1 * NTOK + j];
        }
    }
    __syncthreads();

    for (int r = wid; r < NTOK; r += 4) {
        const bool v2 = (lane + 32 < NTOK);
        float x0 = s[r][lane];
        float x1 = v2 ? s[r][lane + 32] : -1e30f;
        float m = fmaxf(x0, x1);
        #pragma unroll
        for (int off = 16; off > 0; off >>= 1)
            m = fmaxf(m, __shfl_xor_sync(0xffffffffu, m, off));
        float e0 = __expf(x0 - m);
        float e1 = v2 ? __expf(x1 - m) : 0.f;
        float sum = e0 + e1;
        #pragma unroll
        for (int off = 16; off > 0; off >>= 1)
            sum += __shfl_xor_sync(0xffffffffu, sum, off);
        const float inv = 1.f / sum;
        s[r][lane] = e0 * inv;
        if (v2) s[r][lane + 32] = e1 * inv;
    }
    __syncthreads();

    for (int p = tid; p < 25 * HDIM; p += 128) {
        const int i0 = (p >> 5) * 2;
        const int d  = p & 31;
        const int i1 = i0 + 1;
        const bool has1 = (i1 < NTOK);
        const int i1r = has1 ? i1 : i0;

        float acc0 = 0.f, acc1 = 0.f;
        #pragma unroll 7
        for (int j = 0; j < NTOK; j++) {
            const float vv = v[j][d];
            acc0 = fmaf(s[i0][j],  vv, acc0);
            acc1 = fmaf(s[i1r][j], vv, acc1);
        }
        {
            const size_t off = (size_t)(b * NTOK + i0) * DIM + col0 + d;
            __nv_bfloat16 hh = __float2bfloat16(acc0);
            ohi[off] = hh;
            olo[off] = __float2bfloat16(acc0 - __bfloat162float(hh));
        }
        if (has1) {
            const size_t off = (size_t)(b * NTOK + i1) * DIM + col0 + d;
            __nv_bfloat16 hh = __float2bfloat16(acc1);
            ohi[off] = hh;
            olo[off] = __float2bfloat16(acc1 - __bfloat162float(hh));
        }
    }
}

// ---------------------------------------------------------------------------
extern "C" void kernel_launch(void* const* d_in, const int* in_sizes, int n_in,
                              void* d_out, int out_size) {
    const float* x          = (const float*)d_in[0];
    const float* mask       = (const float*)d_in[1];
    const float* qkv_w      = (const float*)d_in[2];
    const float* qkv_b      = (const float*)d_in[3];
    const float* proj_w     = (const float*)d_in[4];
    const float* proj_b     = (const float*)d_in[5];
    const float* bias_table = (const float*)d_in[6];
    float* out = (float*)d_out;

    __nv_bfloat16 *xhi, *xlo, *wqh, *wql, *wph, *wpl, *ahi, *alo;
    float* qkvbuf;
    cudaGetSymbolAddress((void**)&xhi, g_xhi);
    cudaGetSymbolAddress((void**)&xlo, g_xlo);
    cudaGetSymbolAddress((void**)&wqh, g_wqh);
    cudaGetSymbolAddress((void**)&wql, g_wql);
    cudaGetSymbolAddress((void**)&wph, g_wph);
    cudaGetSymbolAddress((void**)&wpl, g_wpl);
    cudaGetSymbolAddress((void**)&ahi, g_ahi);
    cudaGetSymbolAddress((void**)&alo, g_alo);
    cudaGetSymbolAddress((void**)&qkvbuf, g_qkv);

    cudaFuncSetAttribute(gemm_mma, cudaFuncAttributeMaxDynamicSharedMemorySize,
                         GEMM_SMEM);

    {   // split x -> bf16 hi/lo
        const size_t n4 = (size_t)MROWS * KD / 4;
        convert_x_kernel<<<(unsigned)((n4 + 255) / 256), 256>>>(x, xhi, xlo, n4);
    }
    {   // weights: transpose + split
        convert_w_kernel<<<(KD * QKVCOLS + 255) / 256, 256>>>(qkv_w, wqh, wql, KD, QKVCOLS);
        convert_w_kernel<<<(KD * DIM + 255) / 256, 256>>>(proj_w, wph, wpl, KD, DIM);
    }
    {   // QKV GEMM (tensor cores)
        dim3 grid(QKVCOLS / 128, MROWS / 128);
        gemm_mma<<<grid, 256, GEMM_SMEM>>>(xhi, xlo, wqh, wql, qkv_b, qkvbuf, QKVCOLS);
    }
    {   // attention
        dim3 grid(BATCH, NHEAD);
        window_attn_kernel<<<grid, 128>>>(qkvbuf, mask, bias_table, ahi, alo);
    }
    {   // proj GEMM (tensor cores)
        dim3 grid(DIM / 128, MROWS / 128);
        gemm_mma<<<grid, 256, GEMM_SMEM>>>(ahi, alo, wph, wpl, proj_b, out, DIM);
    }
}